// round 1
// baseline (speedup 1.0000x reference)
#include <cuda_runtime.h>
#include <math.h>

#define FILTER_LEN 1024
#define HOP        512
#define CUTOFF     513          // FILTER_LEN/2 + 1
#define BATCH      8
#define TLEN       1048576
#define NFRAMES    2049         // TLEN/HOP + 1
#define XP_LEN     (TLEN + FILTER_LEN)   // 1049600

#define TF 64                   // f-tile (frequencies per block)
#define TN 64                   // n-tile (frames per block)
#define KT 16                   // k chunk

// Reflect-padded signal scratch (static device global: allocation-guard safe)
__device__ float g_xp[BATCH * XP_LEN];

// ---------------------------------------------------------------------------
// Kernel 1: reflect pad  xp[b][p] = x[b][reflect(p-512)]
// ---------------------------------------------------------------------------
__global__ void pad_kernel(const float* __restrict__ x) {
    long long i = (long long)blockIdx.x * blockDim.x + threadIdx.x;
    const long long total = (long long)BATCH * XP_LEN;
    if (i >= total) return;
    int b = (int)(i / XP_LEN);
    int p = (int)(i % XP_LEN);
    int j = p - HOP;                      // pad = 512
    if (j < 0) j = -j;
    else if (j >= TLEN) j = 2 * TLEN - 2 - j;
    g_xp[i] = x[(long long)b * TLEN + j];
}

// ---------------------------------------------------------------------------
// Kernel 2: tiled GEMM + magnitude
//   out[b][f][n] = sqrt( (sum_k bR[f][k]*xp[n*512+k])^2
//                      + (sum_k bI[f][k]*xp[n*512+k])^2 + eps )
// ---------------------------------------------------------------------------
__global__ __launch_bounds__(256, 4)
void stft_kernel(const float* __restrict__ basis,
                 const float* __restrict__ eps_p,
                 float* __restrict__ out)
{
    __shared__ float bsmR[TF][KT + 1];     // [row][k] pad 1: conflict-free stores
    __shared__ float bsmI[TF][KT + 1];
    __shared__ float fsm[KT][TN + 4];      // stride 68 floats: 16B-aligned float4

    const int tid = threadIdx.x;
    const int tx  = tid & 15;              // n direction (16)
    const int ty  = tid >> 4;              // f direction (16)
    const int b   = blockIdx.z;
    const int f0  = blockIdx.y * TF;
    const int n0  = blockIdx.x * TN;

    const float* xp = g_xp + (long long)b * XP_LEN;

    float accR[4][4], accI[4][4];
    #pragma unroll
    for (int i = 0; i < 4; i++)
        #pragma unroll
        for (int j = 0; j < 4; j++) { accR[i][j] = 0.f; accI[i][j] = 0.f; }

    // loader indices
    const int lk = tid & 15;               // basis: k within chunk
    const int lr = tid >> 4;               // basis: row base (0..15)
    const int fnl = tid >> 2;              // frames: local frame (0..63)
    const int fkk = (tid & 3) * 4;         // frames: k group (0,4,8,12)
    const int gn  = n0 + fnl;

    for (int k0 = 0; k0 < FILTER_LEN; k0 += KT) {
        // ---- load basis tile (64 real rows + 64 imag rows) x 16 k ----
        #pragma unroll
        for (int p = 0; p < 4; p++) {
            int row = lr + p * 16;         // 0..63
            int fR  = f0 + row;
            float vr = 0.f, vi = 0.f;
            if (fR < CUTOFF) {
                vr = basis[(long long)fR * FILTER_LEN + k0 + lk];
                vi = basis[(long long)(fR + CUTOFF) * FILTER_LEN + k0 + lk];
            }
            bsmR[row][lk] = vr;
            bsmI[row][lk] = vi;
        }
        // ---- load frames tile: fsm[k][nl] = xp[n*HOP + k0 + k] ----
        if (gn < NFRAMES) {
            const float4 v = *reinterpret_cast<const float4*>(
                xp + (long long)gn * HOP + k0 + fkk);
            fsm[fkk + 0][fnl] = v.x;
            fsm[fkk + 1][fnl] = v.y;
            fsm[fkk + 2][fnl] = v.z;
            fsm[fkk + 3][fnl] = v.w;
        } else {
            fsm[fkk + 0][fnl] = 0.f;
            fsm[fkk + 1][fnl] = 0.f;
            fsm[fkk + 2][fnl] = 0.f;
            fsm[fkk + 3][fnl] = 0.f;
        }
        __syncthreads();

        // ---- compute: 4f x 4n register tile, real+imag accumulators ----
        #pragma unroll
        for (int k = 0; k < KT; k++) {
            float4 f4 = *reinterpret_cast<const float4*>(&fsm[k][tx * 4]);
            float fr[4] = { f4.x, f4.y, f4.z, f4.w };
            float br[4], bi[4];
            #pragma unroll
            for (int i = 0; i < 4; i++) {
                br[i] = bsmR[ty * 4 + i][k];   // broadcast within warp
                bi[i] = bsmI[ty * 4 + i][k];
            }
            #pragma unroll
            for (int i = 0; i < 4; i++)
                #pragma unroll
                for (int j = 0; j < 4; j++) {
                    accR[i][j] = fmaf(br[i], fr[j], accR[i][j]);
                    accI[i][j] = fmaf(bi[i], fr[j], accI[i][j]);
                }
        }
        __syncthreads();
    }

    // ---- epilogue: magnitude + store ----
    const float eps = *eps_p;
    #pragma unroll
    for (int i = 0; i < 4; i++) {
        int f = f0 + ty * 4 + i;
        if (f >= CUTOFF) continue;
        #pragma unroll
        for (int j = 0; j < 4; j++) {
            int n = n0 + tx * 4 + j;
            if (n < NFRAMES) {
                float r = accR[i][j], im = accI[i][j];
                out[((long long)b * CUTOFF + f) * NFRAMES + n] =
                    sqrtf(fmaf(r, r, fmaf(im, im, eps)));
            }
        }
    }
}

// ---------------------------------------------------------------------------
// Launch
// ---------------------------------------------------------------------------
extern "C" void kernel_launch(void* const* d_in, const int* in_sizes, int n_in,
                              void* d_out, int out_size)
{
    const float* x     = (const float*)d_in[0];   // (8, 1048576) fp32
    const float* basis = (const float*)d_in[1];   // (1026, 1024) fp32
    const float* eps   = (const float*)d_in[2];   // scalar fp32
    float* out = (float*)d_out;                   // (8, 513, 2049) fp32

    {
        long long total = (long long)BATCH * XP_LEN;
        int threads = 256;
        int blocks = (int)((total + threads - 1) / threads);
        pad_kernel<<<blocks, threads>>>(x);
    }
    {
        dim3 grid((NFRAMES + TN - 1) / TN,   // 33
                  (CUTOFF + TF - 1) / TF,    // 9
                  BATCH);                    // 8
        stft_kernel<<<grid, 256>>>(basis, eps, out);
    }
}

// round 3
// speedup vs baseline: 3.2081x; 3.2081x over previous
#include <cuda_runtime.h>
#include <cuda_bf16.h>
#include <cstdint>
#include <math.h>

#define FILTER_LEN 1024
#define HOP        512
#define CUTOFF     513
#define BATCH      8
#define TLEN       1048576
#define NFRAMES    2049
#define XP_LEN     (TLEN + FILTER_LEN)     // 1049600

#define MROWS   1152                       // interleaved basis rows, padded (9*128)
#define BM      128                        // block M tile
#define BN      128                        // block N tile
#define KC      64                         // bf16 k per chunk (128 B rows)
#define NK      (FILTER_LEN / KC)          // 16 chunks

// smem per stage: 4 tiles of 128 rows x 128 B
#define SA_HI   0
#define SA_LO   16384
#define SB_HI   32768
#define SB_LO   49152
#define STAGE   65536
#define DSMEM   (2 * STAGE)                // 128 KB

// ---------------- device scratch (static globals: allocation-guard safe) ---
__device__ __nv_bfloat16 g_xp_hi[(size_t)BATCH * XP_LEN];
__device__ __nv_bfloat16 g_xp_lo[(size_t)BATCH * XP_LEN];
__device__ __nv_bfloat16 g_bp_hi[(size_t)MROWS * FILTER_LEN];
__device__ __nv_bfloat16 g_bp_lo[(size_t)MROWS * FILTER_LEN];

// ---------------- helpers ---------------------------------------------------
__device__ __forceinline__ uint32_t smem_u32(const void* p) {
    uint32_t a;
    asm("{ .reg .u64 t; cvta.to.shared.u64 t, %1; cvt.u32.u64 %0, t; }"
        : "=r"(a) : "l"(p));
    return a;
}
__device__ __forceinline__ void cp_async16(uint32_t dst, const void* src, uint32_t sz) {
    asm volatile("cp.async.cg.shared.global [%0], [%1], 16, %2;"
                 :: "r"(dst), "l"(src), "r"(sz) : "memory");
}
__device__ __forceinline__ void cp_commit() {
    asm volatile("cp.async.commit_group;" ::: "memory");
}
template <int N> __device__ __forceinline__ void cp_wait() {
    asm volatile("cp.async.wait_group %0;" :: "n"(N) : "memory");
}
__device__ __forceinline__ void ldsm_x4(uint32_t& r0, uint32_t& r1,
                                        uint32_t& r2, uint32_t& r3, uint32_t addr) {
    asm volatile("ldmatrix.sync.aligned.m8n8.x4.shared.b16 {%0,%1,%2,%3}, [%4];"
                 : "=r"(r0), "=r"(r1), "=r"(r2), "=r"(r3) : "r"(addr));
}
__device__ __forceinline__ void mma_bf16(float* d, const uint32_t* a,
                                         uint32_t b0, uint32_t b1) {
    asm volatile(
        "mma.sync.aligned.m16n8k16.row.col.f32.bf16.bf16.f32 "
        "{%0,%1,%2,%3}, {%4,%5,%6,%7}, {%8,%9}, {%0,%1,%2,%3};"
        : "+f"(d[0]), "+f"(d[1]), "+f"(d[2]), "+f"(d[3])
        : "r"(a[0]), "r"(a[1]), "r"(a[2]), "r"(a[3]), "r"(b0), "r"(b1));
}

// ---------------- prep kernels ---------------------------------------------
__global__ void pad_split_kernel(const float* __restrict__ x) {
    size_t i = (size_t)blockIdx.x * blockDim.x + threadIdx.x;
    if (i >= (size_t)BATCH * XP_LEN) return;
    int b = (int)(i / XP_LEN);
    int p = (int)(i % XP_LEN);
    int j = p - HOP;
    if (j < 0) j = -j;
    else if (j >= TLEN) j = 2 * TLEN - 2 - j;
    float v = x[(size_t)b * TLEN + j];
    __nv_bfloat16 h = __float2bfloat16(v);
    g_xp_hi[i] = h;
    g_xp_lo[i] = __float2bfloat16(v - __bfloat162float(h));
}

// interleave basis rows: bp[2f]=real_f, bp[2f+1]=imag_f; zero-pad to 1152 rows
__global__ void basis_prep_kernel(const float* __restrict__ basis) {
    size_t i = (size_t)blockIdx.x * blockDim.x + threadIdx.x;
    if (i >= (size_t)MROWS * FILTER_LEN) return;
    int g = (int)(i >> 10);
    int k = (int)(i & 1023);
    float v = 0.f;
    if (g < 2 * CUTOFF) {
        int f = g >> 1;
        int src = (g & 1) ? (f + CUTOFF) : f;
        v = basis[(size_t)src * FILTER_LEN + k];
    }
    __nv_bfloat16 h = __float2bfloat16(v);
    g_bp_hi[i] = h;
    g_bp_lo[i] = __float2bfloat16(v - __bfloat162float(h));
}

// ---------------- main GEMM + fused magnitude -------------------------------
__global__ __launch_bounds__(256, 1)
void stft_mma_kernel(const float* __restrict__ eps_p, float* __restrict__ out)
{
    extern __shared__ char dsm[];
    const uint32_t sbase = smem_u32(dsm);

    const int tid  = threadIdx.x;
    const int wid  = tid >> 5;
    const int lane = tid & 31;
    const int b  = blockIdx.z;
    const int m0 = blockIdx.y * BM;
    const int n0 = blockIdx.x * BN;

    const int warp_m = (wid >> 1) * 32;    // 0,32,64,96
    const int warp_n = (wid & 1) * 64;     // 0,64

    // loader geometry: 1024 16B-chunks per tile variant; 4 per thread
    int l_row[4], l_c16[4];
    uint32_t l_soff[4];
    #pragma unroll
    for (int j = 0; j < 4; ++j) {
        int chunk = tid + j * 256;
        l_row[j] = chunk >> 3;
        l_c16[j] = chunk & 7;
        l_soff[j] = (uint32_t)l_row[j] * 128 + (uint32_t)((l_c16[j] ^ (l_row[j] & 7)) * 16);
    }

    const __nv_bfloat16* bpH = g_bp_hi + (size_t)m0 * FILTER_LEN;
    const __nv_bfloat16* bpL = g_bp_lo + (size_t)m0 * FILTER_LEN;
    const __nv_bfloat16* xpH = g_xp_hi + (size_t)b * XP_LEN;
    const __nv_bfloat16* xpL = g_xp_lo + (size_t)b * XP_LEN;

    float acc[2][8][4];
    #pragma unroll
    for (int mt = 0; mt < 2; ++mt)
        #pragma unroll
        for (int nt = 0; nt < 8; ++nt)
            #pragma unroll
            for (int r = 0; r < 4; ++r) acc[mt][nt][r] = 0.f;

    // ldmatrix per-thread geometry
    const int lm_r  = lane & 15;           // row within 16-row tile
    const int lm_s  = lane >> 4;           // 16B column select (0/1)

    auto load_stage = [&](int i) {
        const uint32_t st = sbase + (uint32_t)(i & 1) * STAGE;
        const int k0 = i * KC;
        #pragma unroll
        for (int j = 0; j < 4; ++j) {
            const size_t aoff = (size_t)l_row[j] * FILTER_LEN + k0 + l_c16[j] * 8;
            cp_async16(st + SA_HI + l_soff[j], bpH + aoff, 16);
            cp_async16(st + SA_LO + l_soff[j], bpL + aoff, 16);
            const int n = n0 + l_row[j];
            const uint32_t ok = (n < NFRAMES) ? 16u : 0u;
            const size_t boff = ok ? ((size_t)n * HOP + k0 + l_c16[j] * 8) : 0;
            cp_async16(st + SB_HI + l_soff[j], xpH + boff, ok);
            cp_async16(st + SB_LO + l_soff[j], xpL + boff, ok);
        }
        cp_commit();
    };

    load_stage(0);

    for (int i = 0; i < NK; ++i) {
        if (i + 1 < NK) load_stage(i + 1);
        if (i + 1 < NK) cp_wait<1>(); else cp_wait<0>();
        __syncthreads();

        const uint32_t st = sbase + (uint32_t)(i & 1) * STAGE;

        #pragma unroll
        for (int ks = 0; ks < 4; ++ks) {
            const int c16 = ks * 2 + lm_s;
            // A fragments (hi & lo) for 2 m16 tiles
            uint32_t aH[2][4], aL[2][4];
            #pragma unroll
            for (int mt = 0; mt < 2; ++mt) {
                const int row = warp_m + mt * 16 + lm_r;
                const uint32_t ad = st + (uint32_t)row * 128
                                  + (uint32_t)((c16 ^ (row & 7)) * 16);
                ldsm_x4(aH[mt][0], aH[mt][1], aH[mt][2], aH[mt][3], ad + SA_HI);
                ldsm_x4(aL[mt][0], aL[mt][1], aL[mt][2], aL[mt][3], ad + SA_LO);
            }
            // B groups of n16
            #pragma unroll
            for (int g = 0; g < 4; ++g) {
                const int row = warp_n + g * 16 + lm_r;
                const uint32_t bd = st + (uint32_t)row * 128
                                  + (uint32_t)((c16 ^ (row & 7)) * 16);
                uint32_t bh[4], bl[4];
                ldsm_x4(bh[0], bh[1], bh[2], bh[3], bd + SB_HI);
                ldsm_x4(bl[0], bl[1], bl[2], bl[3], bd + SB_LO);
                #pragma unroll
                for (int sub = 0; sub < 2; ++sub) {
                    const int nt = g * 2 + sub;
                    const uint32_t b0h = sub ? bh[1] : bh[0];
                    const uint32_t b1h = sub ? bh[3] : bh[2];
                    const uint32_t b0l = sub ? bl[1] : bl[0];
                    const uint32_t b1l = sub ? bl[3] : bl[2];
                    #pragma unroll
                    for (int mt = 0; mt < 2; ++mt) {
                        mma_bf16(acc[mt][nt], aH[mt], b0h, b1h);   // hi*hi
                        mma_bf16(acc[mt][nt], aH[mt], b0l, b1l);   // hi*lo
                        mma_bf16(acc[mt][nt], aL[mt], b0h, b1h);   // lo*hi
                    }
                }
            }
        }
        __syncthreads();
    }

    // ---- epilogue: pair R/I fragment rows via shfl_xor(4), magnitude -------
    const float eps = *eps_p;
    const int r4   = lane >> 2;            // fragment row 0..7
    const int c2   = (lane & 3) * 2;       // fragment col base
    const bool real_holder = ((r4 & 1) == 0);

    #pragma unroll
    for (int mt = 0; mt < 2; ++mt) {
        const int mbase = m0 + warp_m + mt * 16;
        #pragma unroll
        for (int nt = 0; nt < 8; ++nt) {
            float p[4];
            #pragma unroll
            for (int r = 0; r < 4; ++r)
                p[r] = __shfl_xor_sync(0xffffffffu, acc[mt][nt][r], 4);
            if (real_holder) {
                const int nb = n0 + warp_n + nt * 8 + c2;
                const int f0r = (mbase + r4) >> 1;
                const int f1r = (mbase + r4 + 8) >> 1;
                #pragma unroll
                for (int cc = 0; cc < 2; ++cc) {
                    const int n = nb + cc;
                    if (n >= NFRAMES) continue;
                    if (f0r < CUTOFF) {
                        float re = acc[mt][nt][cc], im = p[cc];
                        out[((size_t)b * CUTOFF + f0r) * NFRAMES + n] =
                            sqrtf(fmaf(re, re, fmaf(im, im, eps)));
                    }
                    if (f1r < CUTOFF) {
                        float re = acc[mt][nt][2 + cc], im = p[2 + cc];
                        out[((size_t)b * CUTOFF + f1r) * NFRAMES + n] =
                            sqrtf(fmaf(re, re, fmaf(im, im, eps)));
                    }
                }
            }
        }
    }
}

// ---------------- launch ----------------------------------------------------
extern "C" void kernel_launch(void* const* d_in, const int* in_sizes, int n_in,
                              void* d_out, int out_size)
{
    const float* x     = (const float*)d_in[0];   // (8, 1048576) fp32
    const float* basis = (const float*)d_in[1];   // (1026, 1024) fp32
    const float* eps   = (const float*)d_in[2];   // scalar fp32
    float* out = (float*)d_out;                   // (8, 513, 2049) fp32

    {
        size_t total = (size_t)BATCH * XP_LEN;
        pad_split_kernel<<<(unsigned)((total + 255) / 256), 256>>>(x);
    }
    {
        size_t total = (size_t)MROWS * FILTER_LEN;
        basis_prep_kernel<<<(unsigned)((total + 255) / 256), 256>>>(basis);
    }
    {
        cudaFuncSetAttribute(stft_mma_kernel,
                             cudaFuncAttributeMaxDynamicSharedMemorySize, DSMEM);
        dim3 grid((NFRAMES + BN - 1) / BN,   // 17
                  MROWS / BM,                // 9
                  BATCH);                    // 8
        stft_mma_kernel<<<grid, 256, DSMEM>>>(eps, out);
    }
}

// round 4
// speedup vs baseline: 3.4770x; 1.0838x over previous
#include <cuda_runtime.h>
#include <cuda_bf16.h>
#include <cstdint>
#include <math.h>

#define FILTER_LEN 1024
#define HOP        512
#define CUTOFF     513
#define BATCH      8
#define TLEN       1048576
#define NFRAMES    2049
#define XP_LEN     (TLEN + FILTER_LEN)     // 1049600

#define MROWS   1024                       // interleaved rows: f 0..511 (R,I pairs)
#define BM      128
#define BN      128
#define KC      64                         // bf16 k per chunk (128 B rows)
#define NK      (FILTER_LEN / KC)          // 16

#define SA_HI   0
#define SA_LO   16384
#define SB_HI   32768
#define SB_LO   49152
#define STAGE   65536
#define DSMEM   (2 * STAGE)                // 128 KB

#define NREM    (BATCH * (NFRAMES + 512))  // 20488 remainder outputs

// ---------------- device scratch -------------------------------------------
__device__ __nv_bfloat16 g_xp_hi[(size_t)BATCH * XP_LEN];
__device__ __nv_bfloat16 g_xp_lo[(size_t)BATCH * XP_LEN];
__device__ __nv_bfloat16 g_bp_hi[(size_t)MROWS * FILTER_LEN];
__device__ __nv_bfloat16 g_bp_lo[(size_t)MROWS * FILTER_LEN];

// ---------------- helpers ---------------------------------------------------
__device__ __forceinline__ uint32_t smem_u32(const void* p) {
    uint32_t a;
    asm("{ .reg .u64 t; cvta.to.shared.u64 t, %1; cvt.u32.u64 %0, t; }"
        : "=r"(a) : "l"(p));
    return a;
}
__device__ __forceinline__ void cp_async16(uint32_t dst, const void* src) {
    asm volatile("cp.async.cg.shared.global [%0], [%1], 16;"
                 :: "r"(dst), "l"(src) : "memory");
}
__device__ __forceinline__ void cp_commit() {
    asm volatile("cp.async.commit_group;" ::: "memory");
}
template <int N> __device__ __forceinline__ void cp_wait() {
    asm volatile("cp.async.wait_group %0;" :: "n"(N) : "memory");
}
__device__ __forceinline__ void ldsm_x4(uint32_t& r0, uint32_t& r1,
                                        uint32_t& r2, uint32_t& r3, uint32_t addr) {
    asm volatile("ldmatrix.sync.aligned.m8n8.x4.shared.b16 {%0,%1,%2,%3}, [%4];"
                 : "=r"(r0), "=r"(r1), "=r"(r2), "=r"(r3) : "r"(addr));
}
__device__ __forceinline__ void mma_bf16(float* d, const uint32_t* a,
                                         uint32_t b0, uint32_t b1) {
    asm volatile(
        "mma.sync.aligned.m16n8k16.row.col.f32.bf16.bf16.f32 "
        "{%0,%1,%2,%3}, {%4,%5,%6,%7}, {%8,%9}, {%0,%1,%2,%3};"
        : "+f"(d[0]), "+f"(d[1]), "+f"(d[2]), "+f"(d[3])
        : "r"(a[0]), "r"(a[1]), "r"(a[2]), "r"(a[3]), "r"(b0), "r"(b1));
}
__device__ __forceinline__ uint32_t pack2(__nv_bfloat16 a, __nv_bfloat16 b) {
    __nv_bfloat162 t = __halves2bfloat162(a, b);
    return *reinterpret_cast<uint32_t*>(&t);
}

// ---------------- prep: reflect pad + bf16 hi/lo split (float4) ------------
__global__ void pad_split_kernel(const float* __restrict__ x) {
    size_t v = (size_t)blockIdx.x * blockDim.x + threadIdx.x;   // float4 index
    if (v >= (size_t)BATCH * XP_LEN / 4) return;
    const size_t i0 = v * 4;
    const int b = (int)(i0 / XP_LEN);
    const int p0 = (int)(i0 % XP_LEN);
    const float* xb = x + (size_t)b * TLEN;
    __nv_bfloat16 h[4], l[4];
    #pragma unroll
    for (int e = 0; e < 4; ++e) {
        int j = p0 + e - HOP;
        if (j < 0) j = -j;
        else if (j >= TLEN) j = 2 * TLEN - 2 - j;
        float fv = xb[j];
        h[e] = __float2bfloat16(fv);
        l[e] = __float2bfloat16(fv - __bfloat162float(h[e]));
    }
    uint2 ph = make_uint2(pack2(h[0], h[1]), pack2(h[2], h[3]));
    uint2 pl = make_uint2(pack2(l[0], l[1]), pack2(l[2], l[3]));
    *reinterpret_cast<uint2*>(g_xp_hi + i0) = ph;
    *reinterpret_cast<uint2*>(g_xp_lo + i0) = pl;
}

// interleave basis rows: row 2f = real_f, 2f+1 = imag_f (f < 512)
__global__ void basis_prep_kernel(const float* __restrict__ basis) {
    size_t v = (size_t)blockIdx.x * blockDim.x + threadIdx.x;   // float4 index
    if (v >= (size_t)MROWS * FILTER_LEN / 4) return;
    const size_t i0 = v * 4;
    const int g = (int)(i0 >> 10);
    const int k = (int)(i0 & 1023);
    const int f = g >> 1;
    const int src = (g & 1) ? (f + CUTOFF) : f;
    const float4 fv = *reinterpret_cast<const float4*>(basis + (size_t)src * FILTER_LEN + k);
    const float e4[4] = { fv.x, fv.y, fv.z, fv.w };
    __nv_bfloat16 h[4], l[4];
    #pragma unroll
    for (int e = 0; e < 4; ++e) {
        h[e] = __float2bfloat16(e4[e]);
        l[e] = __float2bfloat16(e4[e] - __bfloat162float(h[e]));
    }
    *reinterpret_cast<uint2*>(g_bp_hi + i0) = make_uint2(pack2(h[0], h[1]), pack2(h[2], h[3]));
    *reinterpret_cast<uint2*>(g_bp_lo + i0) = make_uint2(pack2(l[0], l[1]), pack2(l[2], l[3]));
}

// ---------------- main: GEMM (y<8) + fp32 remainder (y==8) -----------------
__global__ __launch_bounds__(256, 1)
void stft_mma_kernel(const float* __restrict__ x,
                     const float* __restrict__ basis,
                     const float* __restrict__ eps_p,
                     float* __restrict__ out)
{
    const int tid  = threadIdx.x;
    const int wid  = tid >> 5;
    const int lane = tid & 31;

    // ======== remainder path: f=512 row + n=2048 column, exact fp32 ========
    if (blockIdx.y == 8) {
        const float eps = *eps_p;
        const int wbase = (int)(blockIdx.z * gridDim.x + blockIdx.x) * 8 + wid;
        for (int o = wbase; o < NREM; o += 16 * 8 * 8) {
            const int b = o / (NFRAMES + 512);
            const int r = o % (NFRAMES + 512);
            int f, n;
            if (r < NFRAMES) { f = 512; n = r; }
            else             { f = r - NFRAMES; n = 2048; }
            const float* bR = basis + (size_t)f * FILTER_LEN;
            const float* bI = basis + (size_t)(f + CUTOFF) * FILTER_LEN;
            const float* xb = x + (size_t)b * TLEN;
            float aR = 0.f, aI = 0.f;
            #pragma unroll 4
            for (int k = lane; k < FILTER_LEN; k += 32) {
                int j = n * HOP + k - HOP;
                if (j < 0) j = -j;
                else if (j >= TLEN) j = 2 * TLEN - 2 - j;
                const float xv = xb[j];
                aR = fmaf(bR[k], xv, aR);
                aI = fmaf(bI[k], xv, aI);
            }
            #pragma unroll
            for (int s = 16; s; s >>= 1) {
                aR += __shfl_xor_sync(0xffffffffu, aR, s);
                aI += __shfl_xor_sync(0xffffffffu, aI, s);
            }
            if (lane == 0)
                out[((size_t)b * CUTOFF + f) * NFRAMES + n] =
                    sqrtf(fmaf(aR, aR, fmaf(aI, aI, eps)));
        }
        return;
    }

    // ======== dense GEMM path: all tiles full, no bounds checks ============
    extern __shared__ char dsm[];
    const uint32_t sbase = smem_u32(dsm);

    const int b  = blockIdx.z;
    const int m0 = blockIdx.y * BM;
    const int n0 = blockIdx.x * BN;

    const int warp_m = (wid >> 1) * 32;
    const int warp_n = (wid & 1) * 64;

    int l_row[4], l_c16[4];
    uint32_t l_soff[4];
    #pragma unroll
    for (int j = 0; j < 4; ++j) {
        int chunk = tid + j * 256;
        l_row[j] = chunk >> 3;
        l_c16[j] = chunk & 7;
        l_soff[j] = (uint32_t)l_row[j] * 128 + (uint32_t)((l_c16[j] ^ (l_row[j] & 7)) * 16);
    }

    const __nv_bfloat16* bpH = g_bp_hi + (size_t)m0 * FILTER_LEN;
    const __nv_bfloat16* bpL = g_bp_lo + (size_t)m0 * FILTER_LEN;
    const __nv_bfloat16* xpH = g_xp_hi + (size_t)b * XP_LEN + (size_t)n0 * HOP;
    const __nv_bfloat16* xpL = g_xp_lo + (size_t)b * XP_LEN + (size_t)n0 * HOP;

    float acc[2][8][4];
    #pragma unroll
    for (int mt = 0; mt < 2; ++mt)
        #pragma unroll
        for (int nt = 0; nt < 8; ++nt)
            #pragma unroll
            for (int r = 0; r < 4; ++r) acc[mt][nt][r] = 0.f;

    const int lm_r = lane & 15;
    const int lm_s = lane >> 4;

    auto load_stage = [&](int i) {
        const uint32_t st = sbase + (uint32_t)(i & 1) * STAGE;
        const int k0 = i * KC;
        #pragma unroll
        for (int j = 0; j < 4; ++j) {
            const size_t aoff = (size_t)l_row[j] * FILTER_LEN + k0 + l_c16[j] * 8;
            cp_async16(st + SA_HI + l_soff[j], bpH + aoff);
            cp_async16(st + SA_LO + l_soff[j], bpL + aoff);
            const size_t boff = (size_t)l_row[j] * HOP + k0 + l_c16[j] * 8;
            cp_async16(st + SB_HI + l_soff[j], xpH + boff);
            cp_async16(st + SB_LO + l_soff[j], xpL + boff);
        }
        cp_commit();
    };

    load_stage(0);

    for (int i = 0; i < NK; ++i) {
        if (i + 1 < NK) { load_stage(i + 1); cp_wait<1>(); }
        else            { cp_wait<0>(); }
        __syncthreads();

        const uint32_t st = sbase + (uint32_t)(i & 1) * STAGE;

        #pragma unroll
        for (int ks = 0; ks < 4; ++ks) {
            const int c16 = ks * 2 + lm_s;
            uint32_t aH[2][4], aL[2][4];
            #pragma unroll
            for (int mt = 0; mt < 2; ++mt) {
                const int row = warp_m + mt * 16 + lm_r;
                const uint32_t ad = st + (uint32_t)row * 128
                                  + (uint32_t)((c16 ^ (row & 7)) * 16);
                ldsm_x4(aH[mt][0], aH[mt][1], aH[mt][2], aH[mt][3], ad + SA_HI);
                ldsm_x4(aL[mt][0], aL[mt][1], aL[mt][2], aL[mt][3], ad + SA_LO);
            }
            #pragma unroll
            for (int g = 0; g < 4; ++g) {
                const int row = warp_n + g * 16 + lm_r;
                const uint32_t bd = st + (uint32_t)row * 128
                                  + (uint32_t)((c16 ^ (row & 7)) * 16);
                uint32_t bh[4], bl[4];
                ldsm_x4(bh[0], bh[1], bh[2], bh[3], bd + SB_HI);
                ldsm_x4(bl[0], bl[1], bl[2], bl[3], bd + SB_LO);
                #pragma unroll
                for (int sub = 0; sub < 2; ++sub) {
                    const int nt = g * 2 + sub;
                    const uint32_t b0h = sub ? bh[1] : bh[0];
                    const uint32_t b1h = sub ? bh[3] : bh[2];
                    const uint32_t b0l = sub ? bl[1] : bl[0];
                    const uint32_t b1l = sub ? bl[3] : bl[2];
                    #pragma unroll
                    for (int mt = 0; mt < 2; ++mt) {
                        mma_bf16(acc[mt][nt], aH[mt], b0h, b1h);
                        mma_bf16(acc[mt][nt], aH[mt], b0l, b1l);
                        mma_bf16(acc[mt][nt], aL[mt], b0h, b1h);
                    }
                }
            }
        }
        __syncthreads();
    }

    // ---- epilogue: pair R/I rows via shfl_xor(4), magnitude, store --------
    const float eps = *eps_p;
    const int r4 = lane >> 2;
    const int c2 = (lane & 3) * 2;
    const bool real_holder = ((r4 & 1) == 0);

    #pragma unroll
    for (int mt = 0; mt < 2; ++mt) {
        const int mbase = m0 + warp_m + mt * 16;
        #pragma unroll
        for (int nt = 0; nt < 8; ++nt) {
            float p[4];
            #pragma unroll
            for (int r = 0; r < 4; ++r)
                p[r] = __shfl_xor_sync(0xffffffffu, acc[mt][nt][r], 4);
            if (real_holder) {
                const int nb = n0 + warp_n + nt * 8 + c2;
                const int f0r = (mbase + r4) >> 1;
                const int f1r = (mbase + r4 + 8) >> 1;
                #pragma unroll
                for (int cc = 0; cc < 2; ++cc) {
                    const int n = nb + cc;
                    float re0 = acc[mt][nt][cc],     im0 = p[cc];
                    float re1 = acc[mt][nt][2 + cc], im1 = p[2 + cc];
                    out[((size_t)b * CUTOFF + f0r) * NFRAMES + n] =
                        sqrtf(fmaf(re0, re0, fmaf(im0, im0, eps)));
                    out[((size_t)b * CUTOFF + f1r) * NFRAMES + n] =
                        sqrtf(fmaf(re1, re1, fmaf(im1, im1, eps)));
                }
            }
        }
    }
}

// ---------------- launch ----------------------------------------------------
extern "C" void kernel_launch(void* const* d_in, const int* in_sizes, int n_in,
                              void* d_out, int out_size)
{
    const float* x     = (const float*)d_in[0];
    const float* basis = (const float*)d_in[1];
    const float* eps   = (const float*)d_in[2];
    float* out = (float*)d_out;

    {
        size_t tot = (size_t)BATCH * XP_LEN / 4;
        pad_split_kernel<<<(unsigned)((tot + 255) / 256), 256>>>(x);
    }
    {
        size_t tot = (size_t)MROWS * FILTER_LEN / 4;
        basis_prep_kernel<<<(unsigned)((tot + 255) / 256), 256>>>(basis);
    }
    {
        cudaFuncSetAttribute(stft_mma_kernel,
                             cudaFuncAttributeMaxDynamicSharedMemorySize, DSMEM);
        dim3 grid(16, 9, BATCH);     // y<8: dense GEMM; y==8: fp32 remainder
        stft_mma_kernel<<<grid, 256, DSMEM>>>(x, basis, eps, out);
    }
}

// round 5
// speedup vs baseline: 4.2087x; 1.2104x over previous
#include <cuda_runtime.h>
#include <cuda_bf16.h>
#include <cstdint>
#include <math.h>

#define FILTER_LEN 1024
#define HOP        512
#define CUTOFF     513
#define BATCH      8
#define TLEN       1048576
#define NFRAMES    2049
#define XP_LEN     (TLEN + FILTER_LEN)     // 1049600

#define MROWS   1024                       // interleaved rows: f 0..511 (R,I pairs)
#define BM      128
#define BN      64
#define KC      64                         // bf16 k per chunk (128 B rows)
#define NK      (FILTER_LEN / KC)          // 16

// stage layout: A(128 rows) hi/lo + B(64 rows) hi/lo, 128 B rows
#define SA_HI   0
#define SA_LO   16384
#define SB_HI   32768
#define SB_LO   40960
#define STAGE   49152                      // 48 KB
#define DSMEM   (2 * STAGE)                // 96 KB -> 2 CTAs/SM

#define NREM    (BATCH * (NFRAMES + 512))  // 20488 remainder outputs

// ---------------- device scratch -------------------------------------------
__device__ __nv_bfloat16 g_xp_hi[(size_t)BATCH * XP_LEN];
__device__ __nv_bfloat16 g_xp_lo[(size_t)BATCH * XP_LEN];
__device__ __nv_bfloat16 g_bp_hi[(size_t)MROWS * FILTER_LEN];
__device__ __nv_bfloat16 g_bp_lo[(size_t)MROWS * FILTER_LEN];

// ---------------- helpers ---------------------------------------------------
__device__ __forceinline__ uint32_t smem_u32(const void* p) {
    uint32_t a;
    asm("{ .reg .u64 t; cvta.to.shared.u64 t, %1; cvt.u32.u64 %0, t; }"
        : "=r"(a) : "l"(p));
    return a;
}
__device__ __forceinline__ void cp_async16(uint32_t dst, const void* src) {
    asm volatile("cp.async.cg.shared.global [%0], [%1], 16;"
                 :: "r"(dst), "l"(src) : "memory");
}
__device__ __forceinline__ void cp_commit() {
    asm volatile("cp.async.commit_group;" ::: "memory");
}
template <int N> __device__ __forceinline__ void cp_wait() {
    asm volatile("cp.async.wait_group %0;" :: "n"(N) : "memory");
}
__device__ __forceinline__ void ldsm_x4(uint32_t& r0, uint32_t& r1,
                                        uint32_t& r2, uint32_t& r3, uint32_t addr) {
    asm volatile("ldmatrix.sync.aligned.m8n8.x4.shared.b16 {%0,%1,%2,%3}, [%4];"
                 : "=r"(r0), "=r"(r1), "=r"(r2), "=r"(r3) : "r"(addr));
}
__device__ __forceinline__ void mma_bf16(float* d, const uint32_t* a,
                                         uint32_t b0, uint32_t b1) {
    asm volatile(
        "mma.sync.aligned.m16n8k16.row.col.f32.bf16.bf16.f32 "
        "{%0,%1,%2,%3}, {%4,%5,%6,%7}, {%8,%9}, {%0,%1,%2,%3};"
        : "+f"(d[0]), "+f"(d[1]), "+f"(d[2]), "+f"(d[3])
        : "r"(a[0]), "r"(a[1]), "r"(a[2]), "r"(a[3]), "r"(b0), "r"(b1));
}
__device__ __forceinline__ uint32_t pack2(__nv_bfloat16 a, __nv_bfloat16 b) {
    __nv_bfloat162 t = __halves2bfloat162(a, b);
    return *reinterpret_cast<uint32_t*>(&t);
}

// ---------------- prep: reflect pad + bf16 hi/lo split (float4) ------------
__global__ void pad_split_kernel(const float* __restrict__ x) {
    size_t v = (size_t)blockIdx.x * blockDim.x + threadIdx.x;
    if (v >= (size_t)BATCH * XP_LEN / 4) return;
    const size_t i0 = v * 4;
    const int b = (int)(i0 / XP_LEN);
    const int p0 = (int)(i0 % XP_LEN);
    const float* xb = x + (size_t)b * TLEN;
    __nv_bfloat16 h[4], l[4];
    #pragma unroll
    for (int e = 0; e < 4; ++e) {
        int j = p0 + e - HOP;
        if (j < 0) j = -j;
        else if (j >= TLEN) j = 2 * TLEN - 2 - j;
        float fv = xb[j];
        h[e] = __float2bfloat16(fv);
        l[e] = __float2bfloat16(fv - __bfloat162float(h[e]));
    }
    *reinterpret_cast<uint2*>(g_xp_hi + i0) = make_uint2(pack2(h[0], h[1]), pack2(h[2], h[3]));
    *reinterpret_cast<uint2*>(g_xp_lo + i0) = make_uint2(pack2(l[0], l[1]), pack2(l[2], l[3]));
}

// interleave basis rows: row 2f = real_f, 2f+1 = imag_f (f < 512)
__global__ void basis_prep_kernel(const float* __restrict__ basis) {
    size_t v = (size_t)blockIdx.x * blockDim.x + threadIdx.x;
    if (v >= (size_t)MROWS * FILTER_LEN / 4) return;
    const size_t i0 = v * 4;
    const int g = (int)(i0 >> 10);
    const int k = (int)(i0 & 1023);
    const int f = g >> 1;
    const int src = (g & 1) ? (f + CUTOFF) : f;
    const float4 fv = *reinterpret_cast<const float4*>(basis + (size_t)src * FILTER_LEN + k);
    const float e4[4] = { fv.x, fv.y, fv.z, fv.w };
    __nv_bfloat16 h[4], l[4];
    #pragma unroll
    for (int e = 0; e < 4; ++e) {
        h[e] = __float2bfloat16(e4[e]);
        l[e] = __float2bfloat16(e4[e] - __bfloat162float(h[e]));
    }
    *reinterpret_cast<uint2*>(g_bp_hi + i0) = make_uint2(pack2(h[0], h[1]), pack2(h[2], h[3]));
    *reinterpret_cast<uint2*>(g_bp_lo + i0) = make_uint2(pack2(l[0], l[1]), pack2(l[2], l[3]));
}

// ---------------- main: GEMM (y<8) + fp32 remainder (y==8) -----------------
__global__ __launch_bounds__(256, 2)
void stft_mma_kernel(const float* __restrict__ x,
                     const float* __restrict__ basis,
                     const float* __restrict__ eps_p,
                     float* __restrict__ out)
{
    const int tid  = threadIdx.x;
    const int wid  = tid >> 5;
    const int lane = tid & 31;

    // ======== remainder: f=512 row + n=2048 column, exact fp32 =============
    if (blockIdx.y == 8) {
        const float eps = *eps_p;
        const int stride = (int)(gridDim.x * gridDim.z) * 8;
        const int wbase = (int)(blockIdx.z * gridDim.x + blockIdx.x) * 8 + wid;
        for (int o = wbase; o < NREM; o += stride) {
            const int b = o / (NFRAMES + 512);
            const int r = o % (NFRAMES + 512);
            int f, n;
            if (r < NFRAMES) { f = 512; n = r; }
            else             { f = r - NFRAMES; n = 2048; }
            const float* bR = basis + (size_t)f * FILTER_LEN;
            const float* bI = basis + (size_t)(f + CUTOFF) * FILTER_LEN;
            const float* xb = x + (size_t)b * TLEN;
            float aR = 0.f, aI = 0.f;
            #pragma unroll 4
            for (int k = lane; k < FILTER_LEN; k += 32) {
                int j = n * HOP + k - HOP;
                if (j < 0) j = -j;
                else if (j >= TLEN) j = 2 * TLEN - 2 - j;
                const float xv = xb[j];
                aR = fmaf(bR[k], xv, aR);
                aI = fmaf(bI[k], xv, aI);
            }
            #pragma unroll
            for (int s = 16; s; s >>= 1) {
                aR += __shfl_xor_sync(0xffffffffu, aR, s);
                aI += __shfl_xor_sync(0xffffffffu, aI, s);
            }
            if (lane == 0)
                out[((size_t)b * CUTOFF + f) * NFRAMES + n] =
                    sqrtf(fmaf(aR, aR, fmaf(aI, aI, eps)));
        }
        return;
    }

    // ======== dense GEMM: 128m x 64n tiles, all full ========================
    extern __shared__ char dsm[];
    const uint32_t sbase = smem_u32(dsm);

    const int b  = blockIdx.z;
    const int m0 = blockIdx.y * BM;
    const int n0 = blockIdx.x * BN;

    const int warp_m = (wid >> 1) * 32;    // 0,32,64,96
    const int warp_n = (wid & 1) * 32;     // 0,32

    // loader geometry: A = 1024 16B chunks (4 rounds), B = 512 (2 rounds)
    int a_row[4], a_c16[4]; uint32_t a_soff[4];
    #pragma unroll
    for (int j = 0; j < 4; ++j) {
        int chunk = tid + j * 256;
        a_row[j] = chunk >> 3;
        a_c16[j] = chunk & 7;
        a_soff[j] = (uint32_t)a_row[j] * 128 + (uint32_t)((a_c16[j] ^ (a_row[j] & 7)) * 16);
    }
    int b_row[2], b_c16[2]; uint32_t b_soff[2];
    #pragma unroll
    for (int j = 0; j < 2; ++j) {
        int chunk = tid + j * 256;
        b_row[j] = chunk >> 3;
        b_c16[j] = chunk & 7;
        b_soff[j] = (uint32_t)b_row[j] * 128 + (uint32_t)((b_c16[j] ^ (b_row[j] & 7)) * 16);
    }

    const __nv_bfloat16* bpH = g_bp_hi + (size_t)m0 * FILTER_LEN;
    const __nv_bfloat16* bpL = g_bp_lo + (size_t)m0 * FILTER_LEN;
    const __nv_bfloat16* xpH = g_xp_hi + (size_t)b * XP_LEN + (size_t)n0 * HOP;
    const __nv_bfloat16* xpL = g_xp_lo + (size_t)b * XP_LEN + (size_t)n0 * HOP;

    float acc[2][4][4];
    #pragma unroll
    for (int mt = 0; mt < 2; ++mt)
        #pragma unroll
        for (int nt = 0; nt < 4; ++nt)
            #pragma unroll
            for (int r = 0; r < 4; ++r) acc[mt][nt][r] = 0.f;

    const int lm_r = lane & 15;
    const int lm_s = lane >> 4;

    auto load_stage = [&](int i) {
        const uint32_t st = sbase + (uint32_t)(i & 1) * STAGE;
        const int k0 = i * KC;
        #pragma unroll
        for (int j = 0; j < 4; ++j) {
            const size_t aoff = (size_t)a_row[j] * FILTER_LEN + k0 + a_c16[j] * 8;
            cp_async16(st + SA_HI + a_soff[j], bpH + aoff);
            cp_async16(st + SA_LO + a_soff[j], bpL + aoff);
        }
        #pragma unroll
        for (int j = 0; j < 2; ++j) {
            const size_t boff = (size_t)b_row[j] * HOP + k0 + b_c16[j] * 8;
            cp_async16(st + SB_HI + b_soff[j], xpH + boff);
            cp_async16(st + SB_LO + b_soff[j], xpL + boff);
        }
        cp_commit();
    };

    load_stage(0);

    for (int i = 0; i < NK; ++i) {
        if (i + 1 < NK) { load_stage(i + 1); cp_wait<1>(); }
        else            { cp_wait<0>(); }
        __syncthreads();

        const uint32_t st = sbase + (uint32_t)(i & 1) * STAGE;

        #pragma unroll
        for (int ks = 0; ks < 4; ++ks) {
            const int c16 = ks * 2 + lm_s;
            uint32_t aH[2][4], aL[2][4];
            #pragma unroll
            for (int mt = 0; mt < 2; ++mt) {
                const int row = warp_m + mt * 16 + lm_r;
                const uint32_t ad = st + (uint32_t)row * 128
                                  + (uint32_t)((c16 ^ (row & 7)) * 16);
                ldsm_x4(aH[mt][0], aH[mt][1], aH[mt][2], aH[mt][3], ad + SA_HI);
                ldsm_x4(aL[mt][0], aL[mt][1], aL[mt][2], aL[mt][3], ad + SA_LO);
            }
            #pragma unroll
            for (int g = 0; g < 2; ++g) {
                const int row = warp_n + g * 16 + lm_r;
                const uint32_t bd = st + (uint32_t)row * 128
                                  + (uint32_t)((c16 ^ (row & 7)) * 16);
                uint32_t bh[4], bl[4];
                ldsm_x4(bh[0], bh[1], bh[2], bh[3], bd + SB_HI);
                ldsm_x4(bl[0], bl[1], bl[2], bl[3], bd + SB_LO);
                #pragma unroll
                for (int sub = 0; sub < 2; ++sub) {
                    const int nt = g * 2 + sub;
                    const uint32_t b0h = sub ? bh[1] : bh[0];
                    const uint32_t b1h = sub ? bh[3] : bh[2];
                    const uint32_t b0l = sub ? bl[1] : bl[0];
                    const uint32_t b1l = sub ? bl[3] : bl[2];
                    #pragma unroll
                    for (int mt = 0; mt < 2; ++mt) {
                        mma_bf16(acc[mt][nt], aH[mt], b0h, b1h);
                        mma_bf16(acc[mt][nt], aH[mt], b0l, b1l);
                        mma_bf16(acc[mt][nt], aL[mt], b0h, b1h);
                    }
                }
            }
        }
        __syncthreads();
    }

    // ---- epilogue: pair R/I rows via shfl_xor(4), magnitude, store --------
    const float eps = *eps_p;
    const int r4 = lane >> 2;
    const int c2 = (lane & 3) * 2;
    const bool real_holder = ((r4 & 1) == 0);

    #pragma unroll
    for (int mt = 0; mt < 2; ++mt) {
        const int mbase = m0 + warp_m + mt * 16;
        #pragma unroll
        for (int nt = 0; nt < 4; ++nt) {
            float p[4];
            #pragma unroll
            for (int r = 0; r < 4; ++r)
                p[r] = __shfl_xor_sync(0xffffffffu, acc[mt][nt][r], 4);
            if (real_holder) {
                const int nb = n0 + warp_n + nt * 8 + c2;
                const int f0r = (mbase + r4) >> 1;
                const int f1r = (mbase + r4 + 8) >> 1;
                #pragma unroll
                for (int cc = 0; cc < 2; ++cc) {
                    const int n = nb + cc;
                    float re0 = acc[mt][nt][cc],     im0 = p[cc];
                    float re1 = acc[mt][nt][2 + cc], im1 = p[2 + cc];
                    out[((size_t)b * CUTOFF + f0r) * NFRAMES + n] =
                        sqrtf(fmaf(re0, re0, fmaf(im0, im0, eps)));
                    out[((size_t)b * CUTOFF + f1r) * NFRAMES + n] =
                        sqrtf(fmaf(re1, re1, fmaf(im1, im1, eps)));
                }
            }
        }
    }
}

// ---------------- launch ----------------------------------------------------
extern "C" void kernel_launch(void* const* d_in, const int* in_sizes, int n_in,
                              void* d_out, int out_size)
{
    const float* x     = (const float*)d_in[0];
    const float* basis = (const float*)d_in[1];
    const float* eps   = (const float*)d_in[2];
    float* out = (float*)d_out;

    {
        size_t tot = (size_t)BATCH * XP_LEN / 4;
        pad_split_kernel<<<(unsigned)((tot + 255) / 256), 256>>>(x);
    }
    {
        size_t tot = (size_t)MROWS * FILTER_LEN / 4;
        basis_prep_kernel<<<(unsigned)((tot + 255) / 256), 256>>>(basis);
    }
    {
        cudaFuncSetAttribute(stft_mma_kernel,
                             cudaFuncAttributeMaxDynamicSharedMemorySize, DSMEM);
        dim3 grid(32, 9, BATCH);     // y<8: dense GEMM; y==8: fp32 remainder
        stft_mma_kernel<<<grid, 256, DSMEM>>>(x, basis, eps, out);
    }
}